// round 2
// baseline (speedup 1.0000x reference)
#include <cuda_runtime.h>
#include <math_constants.h>

#define BATCH 8192
#define DIM 128
#define MARGIN 0.2f
#define EPSV 1e-6f

#define TM 128
#define TN 128
#define TPAD 132
#define JSPLIT 7

// Scratch (no device allocation allowed)
__device__ float g_r1[BATCH];                 // sq1 + 2*eps*s1 + D*eps^2
__device__ float g_r2[BATCH];                 // sq2 - 2*eps*s2
__device__ unsigned int g_posmax[BATCH];      // float bits, dist >= 0 so int compare works
__device__ unsigned int g_negmin[BATCH];
__device__ unsigned char g_tmask[BATCH];
__device__ int g_t_is32;                      // 1 if target buffer is int32, 0 if int64

// ---------------------------------------------------------------------------
// Detect target dtype layout. If the buffer is int64 (values 0/1, little
// endian), every odd 32-bit word is 0. If int32, ~half the odd words are 1.
// Single block, deterministic.
// ---------------------------------------------------------------------------
__global__ void detect_kernel(const int* __restrict__ t32) {
    __shared__ int sacc[256];
    int acc = 0;
    for (int i = threadIdx.x; i < BATCH / 2; i += 256) acc |= t32[2 * i + 1];
    sacc[threadIdx.x] = acc;
    __syncthreads();
    for (int st = 128; st > 0; st >>= 1) {
        if (threadIdx.x < st) sacc[threadIdx.x] |= sacc[threadIdx.x + st];
        __syncthreads();
    }
    if (threadIdx.x == 0) g_t_is32 = (sacc[0] != 0) ? 1 : 0;
}

// ---------------------------------------------------------------------------
// Prep: per-row sums/sumsq for both matrices + init of reductions/masks.
// One warp per row. 2*BATCH rows total.
// ---------------------------------------------------------------------------
__global__ void prep_kernel(const float* __restrict__ e1,
                            const float* __restrict__ e2,
                            const int* __restrict__ t32) {
    int warp = (blockIdx.x * blockDim.x + threadIdx.x) >> 5;
    int lane = threadIdx.x & 31;
    if (warp >= 2 * BATCH) return;
    bool is1 = (warp < BATCH);
    int row = is1 ? warp : warp - BATCH;
    const float* base = is1 ? e1 : e2;
    float4 v = reinterpret_cast<const float4*>(base + (size_t)row * DIM)[lane];
    float s = v.x + v.y + v.z + v.w;
    float q = v.x * v.x + v.y * v.y + v.z * v.z + v.w * v.w;
    #pragma unroll
    for (int o = 16; o > 0; o >>= 1) {
        s += __shfl_xor_sync(0xffffffffu, s, o);
        q += __shfl_xor_sync(0xffffffffu, q, o);
    }
    if (lane == 0) {
        if (is1) {
            g_r1[row] = q + 2.0f * EPSV * s + (float)DIM * EPSV * EPSV;
            g_posmax[row] = 0xFF800000u;   // -inf bits
            g_negmin[row] = 0x7F800000u;   // +inf bits
            int tv = g_t_is32 ? t32[row] : t32[2 * row];  // int64 low word if needed
            g_tmask[row] = (tv == 1) ? 1 : 0;
        } else {
            g_r2[row] = q - 2.0f * EPSV * s;
        }
    }
}

// ---------------------------------------------------------------------------
// Main: fused GEMM + dist + masked max/min.
// Block: 256 threads (16x16), 8x8 micro-tile. TM=TN=128, full K=128 in smem.
// Grid: (64 i-tiles, JSPLIT j-groups). Per-row max/min held in registers
// across the block's j-tiles, merged globally with bitwise atomics.
// ---------------------------------------------------------------------------
extern __shared__ float s_mem[];

__global__ __launch_bounds__(256, 1)
void bht_main_kernel(const float* __restrict__ e1, const float* __restrict__ e2) {
    float* As = s_mem;                 // [DIM][TPAD], As[k][m] = e1[i0+m][k]
    float* Bs = s_mem + DIM * TPAD;    // [DIM][TPAD], Bs[k][n] = e2[j0+n][k]

    const int tid = threadIdx.x;
    const int tx = tid & 15;
    const int ty = tid >> 4;
    const int lane = tid & 31;        // row-within-32 for tile loads
    const int cgrp = tid >> 5;        // 0..7 column group for tile loads
    const int i0 = blockIdx.x * TM;

    // Load A tile once (transpose; stores are conflict-free: lanes hit distinct rows)
    #pragma unroll
    for (int cp = 0; cp < 4; cp++) {
        int col4 = cgrp + cp * 8;     // float4 column index 0..31
        #pragma unroll
        for (int rp = 0; rp < 4; rp++) {
            int row = lane + rp * 32;
            float4 v = reinterpret_cast<const float4*>(e1 + (size_t)(i0 + row) * DIM)[col4];
            As[(4 * col4 + 0) * TPAD + row] = v.x;
            As[(4 * col4 + 1) * TPAD + row] = v.y;
            As[(4 * col4 + 2) * TPAD + row] = v.z;
            As[(4 * col4 + 3) * TPAD + row] = v.w;
        }
    }

    int rows[8];
    #pragma unroll
    for (int u = 0; u < 4; u++) { rows[u] = 4 * ty + u; rows[u + 4] = 64 + 4 * ty + u; }

    float r1v[8], pmax[8], nmin[8];
    #pragma unroll
    for (int u = 0; u < 8; u++) {
        r1v[u] = g_r1[i0 + rows[u]];
        pmax[u] = -CUDART_INF_F;
        nmin[u] = CUDART_INF_F;
    }

    for (int jt = blockIdx.y; jt < BATCH / TN; jt += JSPLIT) {
        const int j0 = jt * TN;
        __syncthreads();   // previous tile fully consumed
        #pragma unroll
        for (int cp = 0; cp < 4; cp++) {
            int col4 = cgrp + cp * 8;
            #pragma unroll
            for (int rp = 0; rp < 4; rp++) {
                int row = lane + rp * 32;
                float4 v = reinterpret_cast<const float4*>(e2 + (size_t)(j0 + row) * DIM)[col4];
                Bs[(4 * col4 + 0) * TPAD + row] = v.x;
                Bs[(4 * col4 + 1) * TPAD + row] = v.y;
                Bs[(4 * col4 + 2) * TPAD + row] = v.z;
                Bs[(4 * col4 + 3) * TPAD + row] = v.w;
            }
        }
        __syncthreads();

        float acc[8][8];
        #pragma unroll
        for (int mi = 0; mi < 8; mi++)
            #pragma unroll
            for (int ni = 0; ni < 8; ni++) acc[mi][ni] = 0.0f;

        #pragma unroll 8
        for (int k = 0; k < DIM; k++) {
            float4 a0 = *reinterpret_cast<const float4*>(&As[k * TPAD + 4 * ty]);
            float4 a1 = *reinterpret_cast<const float4*>(&As[k * TPAD + 64 + 4 * ty]);
            float4 b0 = *reinterpret_cast<const float4*>(&Bs[k * TPAD + 4 * tx]);
            float4 b1 = *reinterpret_cast<const float4*>(&Bs[k * TPAD + 64 + 4 * tx]);
            float a[8] = {a0.x, a0.y, a0.z, a0.w, a1.x, a1.y, a1.z, a1.w};
            float b[8] = {b0.x, b0.y, b0.z, b0.w, b1.x, b1.y, b1.z, b1.w};
            #pragma unroll
            for (int mi = 0; mi < 8; mi++)
                #pragma unroll
                for (int ni = 0; ni < 8; ni++)
                    acc[mi][ni] += a[mi] * b[ni];
        }

        // Epilogue: distance + masked running max/min
        #pragma unroll
        for (int ni = 0; ni < 8; ni++) {
            int n = j0 + ((ni < 4) ? (4 * tx + ni) : (64 + 4 * tx + ni - 4));
            float c2 = g_r2[n];
            bool pos = (g_tmask[n] != 0);
            #pragma unroll
            for (int mi = 0; mi < 8; mi++) {
                float sq = r1v[mi] + c2 - 2.0f * acc[mi][ni];
                float dd = sqrtf(fmaxf(sq, 0.0f));
                if (pos) pmax[mi] = fmaxf(pmax[mi], dd);
                else     nmin[mi] = fminf(nmin[mi], dd);
            }
        }
    }

    // Reduce across the 16 tx lanes sharing the same rows (xor on lane bits 0..3
    // stays inside the same ty group within the warp), then merge globally.
    #pragma unroll
    for (int mi = 0; mi < 8; mi++) {
        float p = pmax[mi], nm = nmin[mi];
        #pragma unroll
        for (int o = 8; o > 0; o >>= 1) {
            p  = fmaxf(p,  __shfl_xor_sync(0xffffffffu, p,  o));
            nm = fminf(nm, __shfl_xor_sync(0xffffffffu, nm, o));
        }
        if (tx == 0) {
            atomicMax(reinterpret_cast<int*>(&g_posmax[i0 + rows[mi]]), __float_as_int(p));
            atomicMin(reinterpret_cast<int*>(&g_negmin[i0 + rows[mi]]), __float_as_int(nm));
        }
    }
}

// ---------------------------------------------------------------------------
// Finalize: masked mean over anchors. Single block => deterministic.
// ---------------------------------------------------------------------------
__global__ void finalize_kernel(float* __restrict__ out) {
    __shared__ float ssum[256];
    __shared__ float scnt[256];
    float s = 0.0f, c = 0.0f;
    for (int i = threadIdx.x; i < BATCH; i += 256) {
        if (g_tmask[i]) {
            float pm = __int_as_float((int)g_posmax[i]);
            float nm = __int_as_float((int)g_negmin[i]);
            s += fmaxf(pm - nm + MARGIN, 0.0f);
            c += 1.0f;
        }
    }
    ssum[threadIdx.x] = s;
    scnt[threadIdx.x] = c;
    __syncthreads();
    for (int st = 128; st > 0; st >>= 1) {
        if (threadIdx.x < st) {
            ssum[threadIdx.x] += ssum[threadIdx.x + st];
            scnt[threadIdx.x] += scnt[threadIdx.x + st];
        }
        __syncthreads();
    }
    if (threadIdx.x == 0) out[0] = ssum[0] / scnt[0];
}

extern "C" void kernel_launch(void* const* d_in, const int* in_sizes, int n_in,
                              void* d_out, int out_size) {
    const float* e1 = (const float*)d_in[0];
    const float* e2 = (const float*)d_in[1];
    const int* tgt = (const int*)d_in[2];
    float* out = (float*)d_out;

    const int smem_bytes = 2 * DIM * TPAD * (int)sizeof(float);  // 135168
    cudaFuncSetAttribute(bht_main_kernel,
                         cudaFuncAttributeMaxDynamicSharedMemorySize, smem_bytes);

    detect_kernel<<<1, 256>>>(tgt);

    // 2*BATCH warps, 8 warps per block
    prep_kernel<<<(2 * BATCH) / 8, 256>>>(e1, e2, tgt);

    dim3 grid(BATCH / TM, JSPLIT);
    bht_main_kernel<<<grid, 256, smem_bytes>>>(e1, e2);

    finalize_kernel<<<1, 256>>>(out);
}

// round 5
// speedup vs baseline: 1.1915x; 1.1915x over previous
#include <cuda_runtime.h>
#include <math_constants.h>
#include <cstdint>

#define BATCH 8192
#define DIM 128
#define MARGIN 0.2f
#define EPSV 1e-6f

#define TM 128
#define TN 128
#define TPAD 132
#define NJT 64
#define NIT 64
#define NJOBS (NIT * NJT)
#define GRID_MAIN 148

// ---------------------------------------------------------------------------
// Scratch (device allocation forbidden)
// ---------------------------------------------------------------------------
__device__ float g_r1[BATCH];                 // |a|^2 + 2eps*sum(a) + D*eps^2
__device__ float g_r2[BATCH];                 // |b|^2 - 2eps*sum(b)
__device__ unsigned int g_posmax[BATCH];      // float bits of max sq-dist over positives
__device__ unsigned int g_negmin[BATCH];      // float bits of min sq-dist over negatives
__device__ unsigned char g_tmask[BATCH];
__device__ int g_t_is32;

// ---------------------------------------------------------------------------
// Packed f32x2 helpers (Blackwell base ISA, no 'a' feature needed)
// ---------------------------------------------------------------------------
__device__ __forceinline__ void fma2(unsigned long long& d,
                                     unsigned long long a, unsigned long long b) {
    asm("fma.rn.f32x2 %0, %1, %2, %0;" : "+l"(d) : "l"(a), "l"(b));
}
__device__ __forceinline__ unsigned long long pack2(float lo, float hi) {
    unsigned long long r;
    asm("mov.b64 %0, {%1, %2};" : "=l"(r) : "f"(lo), "f"(hi));
    return r;
}
__device__ __forceinline__ void unpack2(float& lo, float& hi, unsigned long long v) {
    asm("mov.b64 {%0, %1}, %2;" : "=f"(lo), "=f"(hi) : "l"(v));
}

// ---------------------------------------------------------------------------
// detect target dtype (int32 vs int64 little-endian 0/1)
// ---------------------------------------------------------------------------
__global__ void detect_kernel(const int* __restrict__ t32) {
    __shared__ int sacc[256];
    int acc = 0;
    for (int i = threadIdx.x; i < BATCH / 2; i += 256) acc |= t32[2 * i + 1];
    sacc[threadIdx.x] = acc;
    __syncthreads();
    for (int st = 128; st > 0; st >>= 1) {
        if (threadIdx.x < st) sacc[threadIdx.x] |= sacc[threadIdx.x + st];
        __syncthreads();
    }
    if (threadIdx.x == 0) g_t_is32 = (sacc[0] != 0) ? 1 : 0;
}

// ---------------------------------------------------------------------------
// prep: row constants, reduction init, mask. One warp per row, 2*BATCH rows.
// ---------------------------------------------------------------------------
__global__ void prep_kernel(const float* __restrict__ e1,
                            const float* __restrict__ e2,
                            const int* __restrict__ t32) {
    int warp = (blockIdx.x * blockDim.x + threadIdx.x) >> 5;
    int lane = threadIdx.x & 31;
    if (warp >= 2 * BATCH) return;
    bool is1 = (warp < BATCH);
    int row = is1 ? warp : warp - BATCH;
    const float* base = is1 ? e1 : e2;
    float4 v = reinterpret_cast<const float4*>(base + (size_t)row * DIM)[lane];
    float s = v.x + v.y + v.z + v.w;
    float q = v.x * v.x + v.y * v.y + v.z * v.z + v.w * v.w;
    #pragma unroll
    for (int o = 16; o > 0; o >>= 1) {
        s += __shfl_xor_sync(0xffffffffu, s, o);
        q += __shfl_xor_sync(0xffffffffu, q, o);
    }
    if (lane == 0) {
        if (is1) {
            g_r1[row] = q + 2.0f * EPSV * s + (float)DIM * EPSV * EPSV;
            g_posmax[row] = 0xFF800000u;   // -inf bits
            g_negmin[row] = 0x7F800000u;   // +inf bits
            int tv = g_t_is32 ? t32[row] : t32[2 * row];
            g_tmask[row] = (tv == 1) ? 1 : 0;
        } else {
            g_r2[row] = q - 2.0f * EPSV * s;
        }
    }
}

// ---------------------------------------------------------------------------
// Main: persistent CTAs, fused GEMM (f32x2 FFMA) + sq-dist masked max/min.
// Block 256 threads (16x16), 8x8 micro-tile as 8x4 packed f32x2 accumulators.
// ---------------------------------------------------------------------------
extern __shared__ float s_mem[];

__global__ __launch_bounds__(256, 1)
void bht_main_kernel(const float* __restrict__ e1, const float* __restrict__ e2) {
    float* As = s_mem;                 // [DIM][TPAD], As[k][m] = e1[i0+m][k]
    float* Bs = s_mem + DIM * TPAD;    // [DIM][TPAD], Bs[k][n] = e2[j0+n][k]

    const int tid = threadIdx.x;
    const int tx = tid & 15;
    const int ty = tid >> 4;
    const int lane = tid & 31;        // row-within-32 for tile loads
    const int cgrp = tid >> 5;        // 0..7 column group for tile loads

    int rows[8];
    #pragma unroll
    for (int u = 0; u < 4; u++) { rows[u] = 4 * ty + u; rows[u + 4] = 64 + 4 * ty + u; }

    const int job0 = (NJOBS * blockIdx.x) / GRID_MAIN;
    const int jend = (NJOBS * (blockIdx.x + 1)) / GRID_MAIN;

    int cur_i = -1, i0 = 0;
    float r1v[8], pmax[8], nmin[8];

    for (int job = job0; job < jend; ++job) {
        const int it = job >> 6;
        const int jt = job & (NJT - 1);
        const int j0 = jt * TN;

        __syncthreads();   // previous tile fully consumed before overwrite

        if (it != cur_i) {
            if (cur_i >= 0) {
                #pragma unroll
                for (int mi = 0; mi < 8; mi++) {
                    float p = pmax[mi], nm = nmin[mi];
                    #pragma unroll
                    for (int o = 8; o > 0; o >>= 1) {
                        p  = fmaxf(p,  __shfl_xor_sync(0xffffffffu, p,  o));
                        nm = fminf(nm, __shfl_xor_sync(0xffffffffu, nm, o));
                    }
                    if (tx == 0) {
                        atomicMax(reinterpret_cast<int*>(&g_posmax[i0 + rows[mi]]), __float_as_int(p));
                        atomicMin(reinterpret_cast<int*>(&g_negmin[i0 + rows[mi]]), __float_as_int(nm));
                    }
                }
            }
            i0 = it * TM;
            #pragma unroll
            for (int u = 0; u < 8; u++) {
                r1v[u] = g_r1[i0 + rows[u]];
                pmax[u] = -CUDART_INF_F;
                nmin[u] = CUDART_INF_F;
            }
            // Load A tile (transpose; conflict-free stores)
            #pragma unroll
            for (int cp = 0; cp < 4; cp++) {
                int col4 = cgrp + cp * 8;
                #pragma unroll
                for (int rp = 0; rp < 4; rp++) {
                    int row = lane + rp * 32;
                    float4 v = reinterpret_cast<const float4*>(e1 + (size_t)(i0 + row) * DIM)[col4];
                    As[(4 * col4 + 0) * TPAD + row] = v.x;
                    As[(4 * col4 + 1) * TPAD + row] = v.y;
                    As[(4 * col4 + 2) * TPAD + row] = v.z;
                    As[(4 * col4 + 3) * TPAD + row] = v.w;
                }
            }
            cur_i = it;
        }

        // Load B tile
        #pragma unroll
        for (int cp = 0; cp < 4; cp++) {
            int col4 = cgrp + cp * 8;
            #pragma unroll
            for (int rp = 0; rp < 4; rp++) {
                int row = lane + rp * 32;
                float4 v = reinterpret_cast<const float4*>(e2 + (size_t)(j0 + row) * DIM)[col4];
                Bs[(4 * col4 + 0) * TPAD + row] = v.x;
                Bs[(4 * col4 + 1) * TPAD + row] = v.y;
                Bs[(4 * col4 + 2) * TPAD + row] = v.z;
                Bs[(4 * col4 + 3) * TPAD + row] = v.w;
            }
        }
        __syncthreads();

        unsigned long long acc2[8][4];
        #pragma unroll
        for (int mi = 0; mi < 8; mi++)
            #pragma unroll
            for (int nj = 0; nj < 4; nj++) acc2[mi][nj] = 0ull;   // (+0.0f, +0.0f)

        #pragma unroll 4
        for (int k = 0; k < DIM; k++) {
            float4 a0 = *reinterpret_cast<const float4*>(&As[k * TPAD + 4 * ty]);
            float4 a1 = *reinterpret_cast<const float4*>(&As[k * TPAD + 64 + 4 * ty]);
            float4 b0 = *reinterpret_cast<const float4*>(&Bs[k * TPAD + 4 * tx]);
            float4 b1 = *reinterpret_cast<const float4*>(&Bs[k * TPAD + 64 + 4 * tx]);
            unsigned long long bv[4] = {pack2(b0.x, b0.y), pack2(b0.z, b0.w),
                                        pack2(b1.x, b1.y), pack2(b1.z, b1.w)};
            unsigned long long av[8] = {pack2(a0.x, a0.x), pack2(a0.y, a0.y),
                                        pack2(a0.z, a0.z), pack2(a0.w, a0.w),
                                        pack2(a1.x, a1.x), pack2(a1.y, a1.y),
                                        pack2(a1.z, a1.z), pack2(a1.w, a1.w)};
            #pragma unroll
            for (int mi = 0; mi < 8; mi++)
                #pragma unroll
                for (int nj = 0; nj < 4; nj++)
                    fma2(acc2[mi][nj], av[mi], bv[nj]);
        }

        // Epilogue: squared distance + masked running max/min (sqrt deferred)
        #pragma unroll
        for (int nj = 0; nj < 4; nj++) {
            int nbase = j0 + ((nj < 2) ? (4 * tx + 2 * nj) : (64 + 4 * tx + 2 * (nj - 2)));
            float c2lo = g_r2[nbase];
            float c2hi = g_r2[nbase + 1];
            bool plo = (g_tmask[nbase] != 0);
            bool phi = (g_tmask[nbase + 1] != 0);
            #pragma unroll
            for (int mi = 0; mi < 8; mi++) {
                float dlo, dhi;
                unpack2(dlo, dhi, acc2[mi][nj]);
                float sqlo = fmaf(dlo, -2.0f, r1v[mi] + c2lo);
                float sqhi = fmaf(dhi, -2.0f, r1v[mi] + c2hi);
                if (plo) pmax[mi] = fmaxf(pmax[mi], sqlo);
                else     nmin[mi] = fminf(nmin[mi], sqlo);
                if (phi) pmax[mi] = fmaxf(pmax[mi], sqhi);
                else     nmin[mi] = fminf(nmin[mi], sqhi);
            }
        }
    }

    // Final flush
    if (cur_i >= 0) {
        #pragma unroll
        for (int mi = 0; mi < 8; mi++) {
            float p = pmax[mi], nm = nmin[mi];
            #pragma unroll
            for (int o = 8; o > 0; o >>= 1) {
                p  = fmaxf(p,  __shfl_xor_sync(0xffffffffu, p,  o));
                nm = fminf(nm, __shfl_xor_sync(0xffffffffu, nm, o));
            }
            if (tx == 0) {
                atomicMax(reinterpret_cast<int*>(&g_posmax[i0 + rows[mi]]), __float_as_int(p));
                atomicMin(reinterpret_cast<int*>(&g_negmin[i0 + rows[mi]]), __float_as_int(nm));
            }
        }
    }
}

// ---------------------------------------------------------------------------
// Finalize: sqrt + hinge + masked mean. Single block => deterministic.
// ---------------------------------------------------------------------------
__global__ void finalize_kernel(float* __restrict__ out) {
    __shared__ float ssum[1024];
    __shared__ float scnt[1024];
    float s = 0.0f, c = 0.0f;
    for (int i = threadIdx.x; i < BATCH; i += 1024) {
        if (g_tmask[i]) {
            float pm = sqrtf(fmaxf(__int_as_float((int)g_posmax[i]), 0.0f));
            float nm = sqrtf(fmaxf(__int_as_float((int)g_negmin[i]), 0.0f));
            s += fmaxf(pm - nm + MARGIN, 0.0f);
            c += 1.0f;
        }
    }
    ssum[threadIdx.x] = s;
    scnt[threadIdx.x] = c;
    __syncthreads();
    for (int st = 512; st > 0; st >>= 1) {
        if (threadIdx.x < st) {
            ssum[threadIdx.x] += ssum[threadIdx.x + st];
            scnt[threadIdx.x] += scnt[threadIdx.x + st];
        }
        __syncthreads();
    }
    if (threadIdx.x == 0) out[0] = ssum[0] / scnt[0];
}

extern "C" void kernel_launch(void* const* d_in, const int* in_sizes, int n_in,
                              void* d_out, int out_size) {
    const float* e1 = (const float*)d_in[0];
    const float* e2 = (const float*)d_in[1];
    const int* tgt = (const int*)d_in[2];
    float* out = (float*)d_out;

    const int smem_bytes = 2 * DIM * TPAD * (int)sizeof(float);  // 135168
    cudaFuncSetAttribute(bht_main_kernel,
                         cudaFuncAttributeMaxDynamicSharedMemorySize, smem_bytes);

    detect_kernel<<<1, 256>>>(tgt);
    prep_kernel<<<(2 * BATCH) / 8, 256>>>(e1, e2, tgt);
    bht_main_kernel<<<GRID_MAIN, 256, smem_bytes>>>(e1, e2);
    finalize_kernel<<<1, 1024>>>(out);
}

// round 9
// speedup vs baseline: 2.8195x; 2.3664x over previous
#include <cuda_runtime.h>
#include <cuda_bf16.h>
#include <math_constants.h>
#include <cstdint>

#define BATCH 8192
#define DIM 128
#define MARGIN 0.2f
#define EPSV 1e-6f

#define NJT 64
#define NIT 64
#define NJOBS (NIT * NJT)
#define GRID_MAIN 148

// SMEM layout: padded bf16 tiles, row stride 272 B (136 bf16) for conflict-free LDSM
#define ROWB 272
#define TILE_BYTES (128 * ROWB)        // 34816
#define SO_J    0
#define SO_MASK 512
#define SO_AHI  1024
#define SO_ALO  (SO_AHI + TILE_BYTES)
#define SO_BHI  (SO_ALO + TILE_BYTES)
#define SO_BLO  (SO_BHI + TILE_BYTES)
#define SMEM_TOTAL (SO_BLO + TILE_BYTES)   // 140288

// ---------------------------------------------------------------------------
// Scratch (device allocation forbidden)
// ---------------------------------------------------------------------------
__device__ float g_r1[BATCH];
__device__ float g_r2[BATCH];
__device__ unsigned int g_posmax[BATCH];   // float bits of max sq-dist (positives)
__device__ unsigned int g_negmin[BATCH];   // float bits of min sq-dist (negatives)
__device__ unsigned char g_tmask[BATCH];
__device__ int g_t_is32;
__device__ __align__(16) __nv_bfloat16 g_e1hi[BATCH * DIM];
__device__ __align__(16) __nv_bfloat16 g_e1lo[BATCH * DIM];
__device__ __align__(16) __nv_bfloat16 g_e2hi[BATCH * DIM];
__device__ __align__(16) __nv_bfloat16 g_e2lo[BATCH * DIM];

// ---------------------------------------------------------------------------
// PTX helpers (base ISA only: ldmatrix + mma.sync, no 'a'-suffix features)
// ---------------------------------------------------------------------------
__device__ __forceinline__ uint32_t smem_to_u32(const void* p) {
    uint32_t a;
    asm("{ .reg .u64 t; cvta.to.shared.u64 t, %1; cvt.u32.u64 %0, t; }" : "=r"(a) : "l"(p));
    return a;
}

__device__ __forceinline__ void ldsm4(uint32_t* r, uint32_t addr) {
    asm volatile("ldmatrix.sync.aligned.m8n8.x4.shared.b16 {%0,%1,%2,%3}, [%4];"
                 : "=r"(r[0]), "=r"(r[1]), "=r"(r[2]), "=r"(r[3]) : "r"(addr));
}

__device__ __forceinline__ void mma16816(float* c, const uint32_t* a, const uint32_t* b) {
    asm volatile(
        "mma.sync.aligned.m16n8k16.row.col.f32.bf16.bf16.f32 "
        "{%0,%1,%2,%3}, {%4,%5,%6,%7}, {%8,%9}, {%0,%1,%2,%3};"
        : "+f"(c[0]), "+f"(c[1]), "+f"(c[2]), "+f"(c[3])
        : "r"(a[0]), "r"(a[1]), "r"(a[2]), "r"(a[3]), "r"(b[0]), "r"(b[1]));
}

// ---------------------------------------------------------------------------
// detect target dtype (int32 vs int64 little-endian 0/1)
// ---------------------------------------------------------------------------
__global__ void detect_kernel(const int* __restrict__ t32) {
    __shared__ int sacc[256];
    int acc = 0;
    for (int i = threadIdx.x; i < BATCH / 2; i += 256) acc |= t32[2 * i + 1];
    sacc[threadIdx.x] = acc;
    __syncthreads();
    for (int st = 128; st > 0; st >>= 1) {
        if (threadIdx.x < st) sacc[threadIdx.x] |= sacc[threadIdx.x + st];
        __syncthreads();
    }
    if (threadIdx.x == 0) g_t_is32 = (sacc[0] != 0) ? 1 : 0;
}

// ---------------------------------------------------------------------------
// prep: row constants, reduction init, mask, bf16 hi/lo split matrices.
// One warp per row, 2*BATCH rows.
// ---------------------------------------------------------------------------
__global__ void prep_kernel(const float* __restrict__ e1,
                            const float* __restrict__ e2,
                            const int* __restrict__ t32) {
    int warp = (blockIdx.x * blockDim.x + threadIdx.x) >> 5;
    int lane = threadIdx.x & 31;
    if (warp >= 2 * BATCH) return;
    bool is1 = (warp < BATCH);
    int row = is1 ? warp : warp - BATCH;
    const float* base = is1 ? e1 : e2;
    float4 v = reinterpret_cast<const float4*>(base + (size_t)row * DIM)[lane];

    float xs[4] = {v.x, v.y, v.z, v.w};
    __nv_bfloat16 h[4], l[4];
    #pragma unroll
    for (int i = 0; i < 4; i++) {
        h[i] = __float2bfloat16_rn(xs[i]);
        l[i] = __float2bfloat16_rn(xs[i] - __bfloat162float(h[i]));
    }
    __nv_bfloat16* dh = is1 ? g_e1hi : g_e2hi;
    __nv_bfloat16* dl = is1 ? g_e1lo : g_e2lo;
    int idx = row * DIM + lane * 4;
    __nv_bfloat162 hp0; hp0.x = h[0]; hp0.y = h[1];
    __nv_bfloat162 hp1; hp1.x = h[2]; hp1.y = h[3];
    __nv_bfloat162 lp0; lp0.x = l[0]; lp0.y = l[1];
    __nv_bfloat162 lp1; lp1.x = l[2]; lp1.y = l[3];
    *reinterpret_cast<__nv_bfloat162*>(&dh[idx])     = hp0;
    *reinterpret_cast<__nv_bfloat162*>(&dh[idx + 2]) = hp1;
    *reinterpret_cast<__nv_bfloat162*>(&dl[idx])     = lp0;
    *reinterpret_cast<__nv_bfloat162*>(&dl[idx + 2]) = lp1;

    float s = v.x + v.y + v.z + v.w;
    float q = v.x * v.x + v.y * v.y + v.z * v.z + v.w * v.w;
    #pragma unroll
    for (int o = 16; o > 0; o >>= 1) {
        s += __shfl_xor_sync(0xffffffffu, s, o);
        q += __shfl_xor_sync(0xffffffffu, q, o);
    }
    if (lane == 0) {
        if (is1) {
            g_r1[row] = q + 2.0f * EPSV * s + (float)DIM * EPSV * EPSV;
            g_posmax[row] = 0xFF800000u;
            g_negmin[row] = 0x7F800000u;
            int tv = g_t_is32 ? t32[row] : t32[2 * row];
            g_tmask[row] = (tv == 1) ? 1 : 0;
        } else {
            g_r2[row] = q - 2.0f * EPSV * s;
        }
    }
}

// ---------------------------------------------------------------------------
// Main: persistent CTAs, bf16-split mma.sync GEMM + fused sq-dist max/min.
// 8 warps: 2 (m) x 4 (n); warp tile 64x32; 3 passes (hi*hi, hi*lo, lo*hi).
// ---------------------------------------------------------------------------
extern __shared__ char sm_dyn[];

__device__ __forceinline__ void load_tile(char* sm, int off,
                                          const __nv_bfloat16* __restrict__ g,
                                          int row0, int tid) {
    #pragma unroll
    for (int t = 0; t < 8; t++) {
        int i = tid + t * 256;
        int row = i >> 4;
        int c = i & 15;
        uint4 v = *reinterpret_cast<const uint4*>(g + (size_t)(row0 + row) * DIM + c * 8);
        *reinterpret_cast<uint4*>(sm + off + row * ROWB + c * 16) = v;
    }
}

__global__ __launch_bounds__(256, 1) void bht_mma_kernel() {
    char* sm = sm_dyn;
    const uint32_t smb = smem_to_u32(sm);
    float* s_j = reinterpret_cast<float*>(sm + SO_J);
    unsigned char* s_mask = reinterpret_cast<unsigned char*>(sm + SO_MASK);

    const int tid = threadIdx.x;
    const int wid = tid >> 5;
    const int lane = tid & 31;
    const int tq = lane >> 2;      // 0..7 row within 8
    const int tr = lane & 3;       // 0..3 col pair
    const int warp_m = (wid & 1) * 64;
    const int warp_n = (wid >> 1) * 32;

    // ldmatrix lane address components (byte offsets, pass-invariant part)
    const int a_row = warp_m + (lane & 15);
    const int a_koff = (lane >> 4) * 16;
    const int b_row = warp_n + ((lane & 7) + ((lane >> 4) << 3));
    const int b_koff = ((lane >> 3) & 1) * 16;

    const int job0 = (NJOBS * blockIdx.x) / GRID_MAIN;
    const int jend = (NJOBS * (blockIdx.x + 1)) / GRID_MAIN;

    int cur_i = -1, i0 = 0;
    float r1v[8], pmax[8], nmin[8];

    for (int job = job0; job < jend; ++job) {
        const int it = job >> 6;
        const int jt = job & (NJT - 1);
        const int j0 = jt * 128;

        __syncthreads();   // prior tile fully consumed

        if (it != cur_i) {
            if (cur_i >= 0) {
                #pragma unroll
                for (int idx = 0; idx < 8; idx++) {
                    float p = pmax[idx], nm = nmin[idx];
                    p  = fmaxf(p,  __shfl_xor_sync(0xffffffffu, p,  1));
                    p  = fmaxf(p,  __shfl_xor_sync(0xffffffffu, p,  2));
                    nm = fminf(nm, __shfl_xor_sync(0xffffffffu, nm, 1));
                    nm = fminf(nm, __shfl_xor_sync(0xffffffffu, nm, 2));
                    if (tr == 0) {
                        int row = i0 + warp_m + (idx >> 1) * 16 + (idx & 1) * 8 + tq;
                        atomicMax(reinterpret_cast<int*>(&g_posmax[row]), __float_as_int(p));
                        atomicMin(reinterpret_cast<int*>(&g_negmin[row]), __float_as_int(nm));
                    }
                }
            }
            i0 = it * 128;
            #pragma unroll
            for (int idx = 0; idx < 8; idx++) {
                int row = i0 + warp_m + (idx >> 1) * 16 + (idx & 1) * 8 + tq;
                r1v[idx] = g_r1[row];
                pmax[idx] = -CUDART_INF_F;
                nmin[idx] = CUDART_INF_F;
            }
            load_tile(sm, SO_AHI, g_e1hi, i0, tid);
            load_tile(sm, SO_ALO, g_e1lo, i0, tid);
            cur_i = it;
        }

        load_tile(sm, SO_BHI, g_e2hi, j0, tid);
        load_tile(sm, SO_BLO, g_e2lo, j0, tid);
        if (tid < 128) {
            s_j[tid] = g_r2[j0 + tid];
            s_mask[tid] = g_tmask[j0 + tid];
        }
        __syncthreads();

        float acc[4][4][4];
        #pragma unroll
        for (int mb = 0; mb < 4; mb++)
            #pragma unroll
            for (int nb = 0; nb < 4; nb++)
                #pragma unroll
                for (int e = 0; e < 4; e++) acc[mb][nb][e] = 0.0f;

        #pragma unroll
        for (int pass = 0; pass < 3; pass++) {
            const uint32_t abase = smb + (pass < 2 ? SO_AHI : SO_ALO);
            const uint32_t bbase = smb + (pass == 1 ? SO_BLO : SO_BHI);
            const uint32_t a_addr0 = abase + a_row * ROWB + a_koff;
            const uint32_t b_addr0 = bbase + b_row * ROWB + b_koff;
            #pragma unroll
            for (int k = 0; k < 8; k++) {
                uint32_t af[4][4];
                #pragma unroll
                for (int mb = 0; mb < 4; mb++)
                    ldsm4(af[mb], a_addr0 + mb * 16 * ROWB + k * 32);
                uint32_t bfr[2][4];
                #pragma unroll
                for (int nh = 0; nh < 2; nh++)
                    ldsm4(bfr[nh], b_addr0 + nh * 16 * ROWB + k * 32);
                #pragma unroll
                for (int mb = 0; mb < 4; mb++) {
                    #pragma unroll
                    for (int nb = 0; nb < 4; nb++) {
                        uint32_t bfrag[2] = {bfr[nb >> 1][(nb & 1) * 2],
                                             bfr[nb >> 1][(nb & 1) * 2 + 1]};
                        mma16816(acc[mb][nb], af[mb], bfrag);
                    }
                }
            }
        }

        // Epilogue: squared distance + masked running max/min
        #pragma unroll
        for (int nb = 0; nb < 4; nb++) {
            int col0 = warp_n + nb * 8 + 2 * tr;
            float c2a = s_j[col0];
            float c2b = s_j[col0 + 1];
            bool pa = (s_mask[col0] != 0);
            bool pb = (s_mask[col0 + 1] != 0);
            #pragma unroll
            for (int mb = 0; mb < 4; mb++) {
                float b0 = r1v[mb * 2 + 0];       // row tq
                float b1 = r1v[mb * 2 + 1];       // row tq + 8
                float s00 = fmaf(acc[mb][nb][0], -2.0f, b0 + c2a);
                float s01 = fmaf(acc[mb][nb][1], -2.0f, b0 + c2b);
                float s10 = fmaf(acc[mb][nb][2], -2.0f, b1 + c2a);
                float s11 = fmaf(acc[mb][nb][3], -2.0f, b1 + c2b);
                if (pa) { pmax[mb*2]   = fmaxf(pmax[mb*2],   s00);
                          pmax[mb*2+1] = fmaxf(pmax[mb*2+1], s10); }
                else    { nmin[mb*2]   = fminf(nmin[mb*2],   s00);
                          nmin[mb*2+1] = fminf(nmin[mb*2+1], s10); }
                if (pb) { pmax[mb*2]   = fmaxf(pmax[mb*2],   s01);
                          pmax[mb*2+1] = fmaxf(pmax[mb*2+1], s11); }
                else    { nmin[mb*2]   = fminf(nmin[mb*2],   s01);
                          nmin[mb*2+1] = fminf(nmin[mb*2+1], s11); }
            }
        }
    }

    // Final flush
    if (cur_i >= 0) {
        #pragma unroll
        for (int idx = 0; idx < 8; idx++) {
            float p = pmax[idx], nm = nmin[idx];
            p  = fmaxf(p,  __shfl_xor_sync(0xffffffffu, p,  1));
            p  = fmaxf(p,  __shfl_xor_sync(0xffffffffu, p,  2));
            nm = fminf(nm, __shfl_xor_sync(0xffffffffu, nm, 1));
            nm = fminf(nm, __shfl_xor_sync(0xffffffffu, nm, 2));
            if (tr == 0) {
                int row = i0 + warp_m + (idx >> 1) * 16 + (idx & 1) * 8 + tq;
                atomicMax(reinterpret_cast<int*>(&g_posmax[row]), __float_as_int(p));
                atomicMin(reinterpret_cast<int*>(&g_negmin[row]), __float_as_int(nm));
            }
        }
    }
}

// ---------------------------------------------------------------------------
// Finalize: sqrt + hinge + masked mean. Single block => deterministic.
// ---------------------------------------------------------------------------
__global__ void finalize_kernel(float* __restrict__ out) {
    __shared__ float ssum[1024];
    __shared__ float scnt[1024];
    float s = 0.0f, c = 0.0f;
    for (int i = threadIdx.x; i < BATCH; i += 1024) {
        if (g_tmask[i]) {
            float pm = sqrtf(fmaxf(__int_as_float((int)g_posmax[i]), 0.0f));
            float nm = sqrtf(fmaxf(__int_as_float((int)g_negmin[i]), 0.0f));
            s += fmaxf(pm - nm + MARGIN, 0.0f);
            c += 1.0f;
        }
    }
    ssum[threadIdx.x] = s;
    scnt[threadIdx.x] = c;
    __syncthreads();
    for (int st = 512; st > 0; st >>= 1) {
        if (threadIdx.x < st) {
            ssum[threadIdx.x] += ssum[threadIdx.x + st];
            scnt[threadIdx.x] += scnt[threadIdx.x + st];
        }
        __syncthreads();
    }
    if (threadIdx.x == 0) out[0] = ssum[0] / scnt[0];
}

extern "C" void kernel_launch(void* const* d_in, const int* in_sizes, int n_in,
                              void* d_out, int out_size) {
    const float* e1 = (const float*)d_in[0];
    const float* e2 = (const float*)d_in[1];
    const int* tgt = (const int*)d_in[2];
    float* out = (float*)d_out;

    cudaFuncSetAttribute(bht_mma_kernel,
                         cudaFuncAttributeMaxDynamicSharedMemorySize, SMEM_TOTAL);

    detect_kernel<<<1, 256>>>(tgt);
    prep_kernel<<<(2 * BATCH) / 8, 256>>>(e1, e2, tgt);
    bht_mma_kernel<<<GRID_MAIN, 256, SMEM_TOTAL>>>();
    finalize_kernel<<<1, 1024>>>(out);
}

// round 10
// speedup vs baseline: 4.0158x; 1.4243x over previous
#include <cuda_runtime.h>
#include <cuda_fp16.h>
#include <math_constants.h>
#include <cstdint>

#define BATCH 8192
#define DIM 128
#define MARGIN 0.2f
#define EPSV 1e-6f

#define NJT 64
#define NIT 64
#define NJOBS (NIT * NJT)
#define GRID_MAIN 152

// SMEM: fp16 tiles, row stride 272 B (conflict-free LDSM), double-buffered B
#define ROWB 272
#define TILE_BYTES (128 * ROWB)          // 34816
#define SO_SJ   0                        // 2 x 512 B (j row-constants)
#define SO_MASK 1024                     // 2 x 128 B
#define SO_AHI  2048
#define SO_ALO  (SO_AHI + TILE_BYTES)    // 36864
#define SO_B0   (SO_ALO + TILE_BYTES)    // 71680
#define SO_B1   (SO_B0 + TILE_BYTES)     // 106496
#define SMEM_TOTAL (SO_B1 + TILE_BYTES)  // 141312

// ---------------------------------------------------------------------------
// Scratch (device allocation forbidden)
// ---------------------------------------------------------------------------
__device__ float g_r1[BATCH];
__device__ float g_r2[BATCH];
__device__ unsigned int g_posmax[BATCH];   // float bits of max sq-dist (positives)
__device__ unsigned int g_negmin[BATCH];   // float bits of min sq-dist (negatives)
__device__ __align__(16) unsigned char g_tmask[BATCH];
__device__ unsigned int g_done;
__device__ __align__(16) __half g_e1hi[BATCH * DIM];
__device__ __align__(16) __half g_e1lo[BATCH * DIM];
__device__ __align__(16) __half g_e2hi[BATCH * DIM];

// ---------------------------------------------------------------------------
// PTX helpers (base ISA: ldmatrix, mma.sync, cp.async)
// ---------------------------------------------------------------------------
__device__ __forceinline__ uint32_t smem_to_u32(const void* p) {
    uint32_t a;
    asm("{ .reg .u64 t; cvta.to.shared.u64 t, %1; cvt.u32.u64 %0, t; }" : "=r"(a) : "l"(p));
    return a;
}
__device__ __forceinline__ void ldsm4(uint32_t* r, uint32_t addr) {
    asm volatile("ldmatrix.sync.aligned.m8n8.x4.shared.b16 {%0,%1,%2,%3}, [%4];"
                 : "=r"(r[0]), "=r"(r[1]), "=r"(r[2]), "=r"(r[3]) : "r"(addr));
}
__device__ __forceinline__ void mma16816(float* c, const uint32_t* a,
                                         uint32_t b0, uint32_t b1) {
    asm volatile(
        "mma.sync.aligned.m16n8k16.row.col.f32.f16.f16.f32 "
        "{%0,%1,%2,%3}, {%4,%5,%6,%7}, {%8,%9}, {%0,%1,%2,%3};"
        : "+f"(c[0]), "+f"(c[1]), "+f"(c[2]), "+f"(c[3])
        : "r"(a[0]), "r"(a[1]), "r"(a[2]), "r"(a[3]), "r"(b0), "r"(b1));
}
__device__ __forceinline__ void cp16(uint32_t dst, const void* src) {
    asm volatile("cp.async.cg.shared.global [%0], [%1], 16;" :: "r"(dst), "l"(src));
}
#define CP_COMMIT() asm volatile("cp.async.commit_group;" ::: "memory")
#define CP_WAIT_ALL() asm volatile("cp.async.wait_group 0;" ::: "memory")

// ---------------------------------------------------------------------------
// prep: row constants, reduction init, mask (int32 target), fp16 hi/lo split.
// One warp per row, 2*BATCH rows. Also resets the completion ticket.
// ---------------------------------------------------------------------------
__global__ void prep_kernel(const float* __restrict__ e1,
                            const float* __restrict__ e2,
                            const int* __restrict__ t32) {
    if (blockIdx.x == 0 && threadIdx.x == 0) g_done = 0u;
    int warp = (blockIdx.x * blockDim.x + threadIdx.x) >> 5;
    int lane = threadIdx.x & 31;
    if (warp >= 2 * BATCH) return;
    bool is1 = (warp < BATCH);
    int row = is1 ? warp : warp - BATCH;
    const float* base = is1 ? e1 : e2;
    float4 v = reinterpret_cast<const float4*>(base + (size_t)row * DIM)[lane];

    float xs[4] = {v.x, v.y, v.z, v.w};
    __half h[4], l[4];
    #pragma unroll
    for (int i = 0; i < 4; i++) {
        h[i] = __float2half_rn(xs[i]);
        l[i] = __float2half_rn(xs[i] - __half2float(h[i]));
    }
    int idx = row * DIM + lane * 4;
    __half2 hp0; hp0.x = h[0]; hp0.y = h[1];
    __half2 hp1; hp1.x = h[2]; hp1.y = h[3];
    __half* dh = is1 ? g_e1hi : g_e2hi;
    *reinterpret_cast<__half2*>(&dh[idx])     = hp0;
    *reinterpret_cast<__half2*>(&dh[idx + 2]) = hp1;
    if (is1) {
        __half2 lp0; lp0.x = l[0]; lp0.y = l[1];
        __half2 lp1; lp1.x = l[2]; lp1.y = l[3];
        *reinterpret_cast<__half2*>(&g_e1lo[idx])     = lp0;
        *reinterpret_cast<__half2*>(&g_e1lo[idx + 2]) = lp1;
    }

    float s = v.x + v.y + v.z + v.w;
    float q = v.x * v.x + v.y * v.y + v.z * v.z + v.w * v.w;
    #pragma unroll
    for (int o = 16; o > 0; o >>= 1) {
        s += __shfl_xor_sync(0xffffffffu, s, o);
        q += __shfl_xor_sync(0xffffffffu, q, o);
    }
    if (lane == 0) {
        if (is1) {
            g_r1[row] = q + 2.0f * EPSV * s + (float)DIM * EPSV * EPSV;
            g_posmax[row] = 0xFF800000u;
            g_negmin[row] = 0x7F800000u;
            g_tmask[row] = (t32[row] == 1) ? 1 : 0;
        } else {
            g_r2[row] = q - 2.0f * EPSV * s;
        }
    }
}

// ---------------------------------------------------------------------------
// Main: persistent CTAs, fp16-split 2-pass mma.sync GEMM + sq-dist max/min.
// 8 warps as 4(m) x 2(n); warp tile 32x64. Ahi cached in registers per
// i-strip; B double-buffered via cp.async. Last CTA folds in finalization.
// ---------------------------------------------------------------------------
extern __shared__ char sm_dyn[];

__device__ __forceinline__ void issue_tile(uint32_t smb, int off, const __half* g,
                                           int row0, int tid) {
    #pragma unroll
    for (int t = 0; t < 8; t++) {
        int i = tid + t * 256;
        int row = i >> 4;
        int c = i & 15;
        cp16(smb + off + row * ROWB + c * 16, g + (size_t)(row0 + row) * DIM + c * 8);
    }
}

__global__ __launch_bounds__(256, 1) void bht_mma_kernel(float* __restrict__ out) {
    char* sm = sm_dyn;
    const uint32_t smb = smem_to_u32(sm);
    float* s_j = reinterpret_cast<float*>(sm + SO_SJ);
    unsigned char* s_mask = reinterpret_cast<unsigned char*>(sm + SO_MASK);

    const int tid = threadIdx.x;
    const int wid = tid >> 5;
    const int lane = tid & 31;
    const int tq = lane >> 2;
    const int tr = lane & 3;
    const int warp_m = (wid >> 1) * 32;
    const int warp_n = (wid & 1) * 64;

    const int a_off = (warp_m + (lane & 15)) * ROWB + (lane >> 4) * 16;
    const int b_off = (warp_n + (lane & 7) + ((lane >> 4) << 3)) * ROWB
                    + ((lane >> 3) & 1) * 16;

    const int job0 = (NJOBS * blockIdx.x) / GRID_MAIN;
    const int jend = (NJOBS * (blockIdx.x + 1)) / GRID_MAIN;

    int cur_i = -1, i0 = 0, p = 0;
    uint32_t ahi[8][2][4];
    float r1v[4], pmax[4], nmin[4];

    // prologue: first job's B tile + row constants into slot 0
    {
        const int j0 = (job0 & (NJT - 1)) * 128;
        issue_tile(smb, SO_B0, g_e2hi, j0, tid);
        if (tid < 32) cp16(smb + SO_SJ + tid * 16, g_r2 + j0 + tid * 4);
        else if (tid < 40) cp16(smb + SO_MASK + (tid - 32) * 16, g_tmask + j0 + (tid - 32) * 16);
        CP_COMMIT();
    }

    for (int job = job0; job < jend; ++job) {
        const int it = job >> 6;
        const int jt = job & (NJT - 1);
        bool ichg = (it != cur_i);

        if (ichg) {
            // flush previous strip
            if (cur_i >= 0) {
                #pragma unroll
                for (int idx = 0; idx < 4; idx++) {
                    float pv = pmax[idx], nv = nmin[idx];
                    pv = fmaxf(pv, __shfl_xor_sync(0xffffffffu, pv, 1));
                    pv = fmaxf(pv, __shfl_xor_sync(0xffffffffu, pv, 2));
                    nv = fminf(nv, __shfl_xor_sync(0xffffffffu, nv, 1));
                    nv = fminf(nv, __shfl_xor_sync(0xffffffffu, nv, 2));
                    if (tr == 0) {
                        int row = i0 + warp_m + (idx >> 1) * 16 + (idx & 1) * 8 + tq;
                        atomicMax(reinterpret_cast<int*>(&g_posmax[row]), __float_as_int(pv));
                        atomicMin(reinterpret_cast<int*>(&g_negmin[row]), __float_as_int(nv));
                    }
                }
            }
            i0 = it * 128;
            __syncthreads();   // all readers done with old A before overwrite
            issue_tile(smb, SO_AHI, g_e1hi, i0, tid);
            issue_tile(smb, SO_ALO, g_e1lo, i0, tid);
            CP_COMMIT();
        }

        CP_WAIT_ALL();
        __syncthreads();       // slot p (and A, if reloaded) visible to all

        if (ichg) {
            #pragma unroll
            for (int k = 0; k < 8; k++)
                #pragma unroll
                for (int mb = 0; mb < 2; mb++)
                    ldsm4(ahi[k][mb], smb + SO_AHI + a_off + mb * 16 * ROWB + k * 32);
            #pragma unroll
            for (int idx = 0; idx < 4; idx++) {
                int row = i0 + warp_m + (idx >> 1) * 16 + (idx & 1) * 8 + tq;
                r1v[idx] = g_r1[row];
                pmax[idx] = -CUDART_INF_F;
                nmin[idx] = CUDART_INF_F;
            }
            cur_i = it;
        }

        // issue next job's B into the other slot (overlaps with compute below)
        if (job + 1 < jend) {
            const int nj0 = ((job + 1) & (NJT - 1)) * 128;
            const int so_b = p ? SO_B0 : SO_B1;
            const int so_j = SO_SJ + (p ^ 1) * 512;
            const int so_m = SO_MASK + (p ^ 1) * 128;
            issue_tile(smb, so_b, g_e2hi, nj0, tid);
            if (tid < 32) cp16(smb + so_j + tid * 16, g_r2 + nj0 + tid * 4);
            else if (tid < 40) cp16(smb + so_m + (tid - 32) * 16, g_tmask + nj0 + (tid - 32) * 16);
            CP_COMMIT();
        }

        // ---- compute on slot p ----
        const uint32_t bbase = smb + (p ? SO_B1 : SO_B0) + b_off;
        float acc[2][8][4];
        #pragma unroll
        for (int mb = 0; mb < 2; mb++)
            #pragma unroll
            for (int nb = 0; nb < 8; nb++)
                #pragma unroll
                for (int e = 0; e < 4; e++) acc[mb][nb][e] = 0.0f;

        #pragma unroll
        for (int k = 0; k < 8; k++) {
            uint32_t bfr[4][4];
            #pragma unroll
            for (int nh = 0; nh < 4; nh++)
                ldsm4(bfr[nh], bbase + nh * 16 * ROWB + k * 32);
            uint32_t alo[2][4];
            #pragma unroll
            for (int mb = 0; mb < 2; mb++)
                ldsm4(alo[mb], smb + SO_ALO + a_off + mb * 16 * ROWB + k * 32);
            #pragma unroll
            for (int nb = 0; nb < 8; nb++) {
                uint32_t b0 = bfr[nb >> 1][(nb & 1) * 2];
                uint32_t b1 = bfr[nb >> 1][(nb & 1) * 2 + 1];
                mma16816(acc[0][nb], ahi[k][0], b0, b1);
                mma16816(acc[1][nb], ahi[k][1], b0, b1);
            }
            #pragma unroll
            for (int nb = 0; nb < 8; nb++) {
                uint32_t b0 = bfr[nb >> 1][(nb & 1) * 2];
                uint32_t b1 = bfr[nb >> 1][(nb & 1) * 2 + 1];
                mma16816(acc[0][nb], alo[0], b0, b1);
                mma16816(acc[1][nb], alo[1], b0, b1);
            }
        }

        // ---- epilogue: squared distance + masked running max/min ----
        const float* sjp = s_j + p * 128;
        const unsigned char* smp = s_mask + p * 128;
        #pragma unroll
        for (int nb = 0; nb < 8; nb++) {
            int col0 = warp_n + nb * 8 + 2 * tr;
            float c2a = sjp[col0];
            float c2b = sjp[col0 + 1];
            bool pa = (smp[col0] != 0);
            bool pb = (smp[col0 + 1] != 0);
            #pragma unroll
            for (int mb = 0; mb < 2; mb++) {
                float b0 = r1v[mb * 2 + 0];
                float b1 = r1v[mb * 2 + 1];
                float s00 = fmaf(acc[mb][nb][0], -2.0f, b0 + c2a);
                float s01 = fmaf(acc[mb][nb][1], -2.0f, b0 + c2b);
                float s10 = fmaf(acc[mb][nb][2], -2.0f, b1 + c2a);
                float s11 = fmaf(acc[mb][nb][3], -2.0f, b1 + c2b);
                if (pa) { pmax[mb*2]   = fmaxf(pmax[mb*2],   s00);
                          pmax[mb*2+1] = fmaxf(pmax[mb*2+1], s10); }
                else    { nmin[mb*2]   = fminf(nmin[mb*2],   s00);
                          nmin[mb*2+1] = fminf(nmin[mb*2+1], s10); }
                if (pb) { pmax[mb*2]   = fmaxf(pmax[mb*2],   s01);
                          pmax[mb*2+1] = fmaxf(pmax[mb*2+1], s11); }
                else    { nmin[mb*2]   = fminf(nmin[mb*2],   s01);
                          nmin[mb*2+1] = fminf(nmin[mb*2+1], s11); }
            }
        }
        p ^= 1;
    }

    // final flush
    if (cur_i >= 0) {
        #pragma unroll
        for (int idx = 0; idx < 4; idx++) {
            float pv = pmax[idx], nv = nmin[idx];
            pv = fmaxf(pv, __shfl_xor_sync(0xffffffffu, pv, 1));
            pv = fmaxf(pv, __shfl_xor_sync(0xffffffffu, pv, 2));
            nv = fminf(nv, __shfl_xor_sync(0xffffffffu, nv, 1));
            nv = fminf(nv, __shfl_xor_sync(0xffffffffu, nv, 2));
            if (tr == 0) {
                int row = i0 + warp_m + (idx >> 1) * 16 + (idx & 1) * 8 + tq;
                atomicMax(reinterpret_cast<int*>(&g_posmax[row]), __float_as_int(pv));
                atomicMin(reinterpret_cast<int*>(&g_negmin[row]), __float_as_int(nv));
            }
        }
    }

    // ---- last-CTA finalization ----
    __threadfence();
    __syncthreads();
    __shared__ unsigned int s_ticket;
    if (tid == 0) s_ticket = atomicAdd(&g_done, 1u);
    __syncthreads();
    if (s_ticket == GRID_MAIN - 1) {
        __threadfence();
        __shared__ float ssum[256];
        __shared__ float scnt[256];
        float s = 0.0f, c = 0.0f;
        for (int i = tid; i < BATCH; i += 256) {
            if (g_tmask[i]) {
                float pm = sqrtf(fmaxf(__int_as_float((int)g_posmax[i]), 0.0f));
                float nm = sqrtf(fmaxf(__int_as_float((int)g_negmin[i]), 0.0f));
                s += fmaxf(pm - nm + MARGIN, 0.0f);
                c += 1.0f;
            }
        }
        ssum[tid] = s;
        scnt[tid] = c;
        __syncthreads();
        for (int st = 128; st > 0; st >>= 1) {
            if (tid < st) { ssum[tid] += ssum[tid + st]; scnt[tid] += scnt[tid + st]; }
            __syncthreads();
        }
        if (tid == 0) out[0] = ssum[0] / scnt[0];
    }
}

extern "C" void kernel_launch(void* const* d_in, const int* in_sizes, int n_in,
                              void* d_out, int out_size) {
    const float* e1 = (const float*)d_in[0];
    const float* e2 = (const float*)d_in[1];
    const int* tgt = (const int*)d_in[2];
    float* out = (float*)d_out;

    cudaFuncSetAttribute(bht_mma_kernel,
                         cudaFuncAttributeMaxDynamicSharedMemorySize, SMEM_TOTAL);

    prep_kernel<<<(2 * BATCH) / 8, 256>>>(e1, e2, tgt);
    bht_mma_kernel<<<GRID_MAIN, 256, SMEM_TOTAL>>>(out);
}